// round 11
// baseline (speedup 1.0000x reference)
#include <cuda_runtime.h>
#include <cuda_fp16.h>

// ---------------------------------------------------------------------------
// GAT layer, folded + CSR softmax-aggregate, overlapped:
//   main:  prep -> gemm(64x128 tiles, fp16 z, fused st epilogue) -> join ->
//          build -> aggregate
//   s2  :  edge_dot (DRAM-bound, no gemm dep) -> scan   [concurrent w/ gemm]
// ---------------------------------------------------------------------------

#define MAX_NODES 20000
#define PAD_NODES 20480   /* 1024 * 20 */
#define MAX_EDGES 640000

__device__ __align__(16) __half2 g_zh[MAX_NODES * 64];
__device__ __align__(8)  float2  g_st[MAX_NODES];
__device__ __align__(16) float   g_c[64];
__device__ float                 g_vdot[MAX_EDGES];
__device__ __align__(16) int     g_cnt[PAD_NODES];
__device__ __align__(16) int     g_off[PAD_NODES];
__device__ __align__(16) int     g_cur[PAD_NODES];
__device__ __align__(8) float2   g_pcsr[MAX_EDGES];   // (e, src-as-float-bits)

// -- prep: c = We^T a_e ; zero padded histogram --------------------------------
__global__ void k_prep(const float* __restrict__ We,
                       const float* __restrict__ Wa) {
    int t = blockIdx.x * blockDim.x + threadIdx.x;
    if (t < 64) {
        float acc = 0.f;
#pragma unroll 8
        for (int o = 0; o < 128; o++) acc += We[o * 64 + t] * Wa[256 + o];
        g_c[t] = acc;
    }
    if (t < PAD_NODES) g_cnt[t] = 0;
}

// -- edge feature dot, fully coalesced, 8 edges/warp + fused histogram --------
__global__ __launch_bounds__(256) void k_edge_dot(const float4* __restrict__ fe4,
                                                  const int* __restrict__ dst,
                                                  int n_edges) {
    int w = (blockIdx.x * blockDim.x + threadIdx.x) >> 5;
    int lane = threadIdx.x & 31;
    if (w * 8 >= n_edges) return;
    int total4 = n_edges * 16;
    float4 cc = __ldg((const float4*)g_c + (lane & 15));
    float p[4];
#pragma unroll
    for (int k = 0; k < 4; k++) {
        int idx = w * 128 + k * 32 + lane;
        float4 v = (idx < total4) ? fe4[idx] : make_float4(0.f, 0.f, 0.f, 0.f);
        p[k] = v.x * cc.x + v.y * cc.y + v.z * cc.z + v.w * cc.w;
    }
#pragma unroll
    for (int o = 1; o < 16; o <<= 1) {
#pragma unroll
        for (int k = 0; k < 4; k++)
            p[k] += __shfl_xor_sync(0xFFFFFFFFu, p[k], o);
    }
    if ((lane & 15) == 0) {
        int g = lane >> 4;
#pragma unroll
        for (int k = 0; k < 4; k++) {
            int eid = w * 8 + 2 * k + g;
            if (eid < n_edges) {
                g_vdot[eid] = p[k];
                atomicAdd(&g_cnt[dst[eid]], 1);
            }
        }
    }
}

// -- z = A @ B^T, 64x128 tile (TM=4,TN=8), fp16 z store, fused st epilogue -----
__global__ __launch_bounds__(256) void k_gemm(const float* __restrict__ A,
                                              const float* __restrict__ B,
                                              const float* __restrict__ Wa,
                                              int M) {
    __shared__ float As[16][68];
    __shared__ float Bs[16][132];
    const int tid = threadIdx.x;
    const int blockRow = blockIdx.x * 64;
    const int tr = tid >> 4;          // 0..15 -> 4 rows each
    const int tc = tid & 15;          // 0..15 -> 8 cols each
    const int lrow64 = tid >> 2;      // 0..63
    const int lrow128 = tid >> 1;     // 0..127
    const int lcolA = (tid & 3) * 4;  // 0,4,8,12
    const int lcolB = (tid & 1) * 8;  // 0,8

    float acc[4][8];
#pragma unroll
    for (int i = 0; i < 4; i++)
#pragma unroll
        for (int j = 0; j < 8; j++) acc[i][j] = 0.f;

    for (int kt = 0; kt < 128; kt += 16) {
        {
            int gm = blockRow + lrow64;
            float4 v = (gm < M)
                           ? *(const float4*)&A[(size_t)gm * 128 + kt + lcolA]
                           : make_float4(0.f, 0.f, 0.f, 0.f);
            As[lcolA + 0][lrow64] = v.x; As[lcolA + 1][lrow64] = v.y;
            As[lcolA + 2][lrow64] = v.z; As[lcolA + 3][lrow64] = v.w;
        }
        {
            float4 v0 = *(const float4*)&B[(size_t)lrow128 * 128 + kt + lcolB];
            float4 v1 = *(const float4*)&B[(size_t)lrow128 * 128 + kt + lcolB + 4];
            Bs[lcolB + 0][lrow128] = v0.x; Bs[lcolB + 1][lrow128] = v0.y;
            Bs[lcolB + 2][lrow128] = v0.z; Bs[lcolB + 3][lrow128] = v0.w;
            Bs[lcolB + 4][lrow128] = v1.x; Bs[lcolB + 5][lrow128] = v1.y;
            Bs[lcolB + 6][lrow128] = v1.z; Bs[lcolB + 7][lrow128] = v1.w;
        }
        __syncthreads();
#pragma unroll
        for (int k = 0; k < 16; k++) {
            float ra[4], rb[8];
#pragma unroll
            for (int i = 0; i < 4; i++) ra[i] = As[k][tr * 4 + i];
#pragma unroll
            for (int j = 0; j < 8; j++) rb[j] = Bs[k][tc * 8 + j];
#pragma unroll
            for (int i = 0; i < 4; i++)
#pragma unroll
                for (int j = 0; j < 8; j++) acc[i][j] += ra[i] * rb[j];
        }
        __syncthreads();
    }

    // store z tile as fp16
#pragma unroll
    for (int i = 0; i < 4; i++) {
        int gm = blockRow + tr * 4 + i;
        if (gm < M) {
            __half2 q[4];
#pragma unroll
            for (int j = 0; j < 4; j++)
                q[j] = __float22half2_rn(
                    make_float2(acc[i][2 * j], acc[i][2 * j + 1]));
            *(uint4*)&g_zh[(size_t)gm * 64 + tc * 4] = *(uint4*)q;
        }
    }

    // fused epilogue: per-row dots with a_src / a_dst
    float asv[8], adv[8];
#pragma unroll
    for (int j = 0; j < 8; j++) {
        asv[j] = __ldg(Wa + tc * 8 + j);
        adv[j] = __ldg(Wa + 128 + tc * 8 + j);
    }
#pragma unroll
    for (int i = 0; i < 4; i++) {
        float s = 0.f, t = 0.f;
#pragma unroll
        for (int j = 0; j < 8; j++) {
            s += acc[i][j] * asv[j];
            t += acc[i][j] * adv[j];
        }
#pragma unroll
        for (int o = 1; o < 16; o <<= 1) {
            s += __shfl_xor_sync(0xFFFFFFFFu, s, o);
            t += __shfl_xor_sync(0xFFFFFFFFu, t, o);
        }
        int gm = blockRow + tr * 4 + i;
        if (tc == 0 && gm < M) g_st[gm] = make_float2(s, t);
    }
}

// -- exclusive scan over padded 20480 (runs on s2 after edge_dot) --------------
__global__ __launch_bounds__(1024) void k_scan() {
    __shared__ int wsum[32];
    const int tid = threadIdx.x;
    const int lane = tid & 31, wid = tid >> 5;
    const int lo = tid * 20;

    int vals[20];
#pragma unroll
    for (int k = 0; k < 5; k++) {
        int4 v = *(const int4*)&g_cnt[lo + k * 4];
        vals[k * 4 + 0] = v.x; vals[k * 4 + 1] = v.y;
        vals[k * 4 + 2] = v.z; vals[k * 4 + 3] = v.w;
    }

    int local = 0;
#pragma unroll
    for (int i = 0; i < 20; i++) local += vals[i];

    int v = local;
#pragma unroll
    for (int o = 1; o < 32; o <<= 1) {
        int u = __shfl_up_sync(0xFFFFFFFFu, v, o);
        if (lane >= o) v += u;
    }
    if (lane == 31) wsum[wid] = v;
    __syncthreads();
    if (wid == 0) {
        int wv = wsum[lane];
#pragma unroll
        for (int o = 1; o < 32; o <<= 1) {
            int u = __shfl_up_sync(0xFFFFFFFFu, wv, o);
            if (lane >= o) wv += u;
        }
        wsum[lane] = wv;
    }
    __syncthreads();
    int run = v - local + (wid > 0 ? wsum[wid - 1] : 0);

    int pref[20];
#pragma unroll
    for (int i = 0; i < 20; i++) { pref[i] = run; run += vals[i]; }
#pragma unroll
    for (int k = 0; k < 5; k++) {
        int4 pv = make_int4(pref[k * 4 + 0], pref[k * 4 + 1],
                            pref[k * 4 + 2], pref[k * 4 + 3]);
        *(int4*)&g_off[lo + k * 4] = pv;
        *(int4*)&g_cur[lo + k * 4] = pv;
    }
}

// -- build CSR-ordered packed (e, src), fused logit + leaky-relu ---------------
__global__ void k_build(const int* __restrict__ src,
                        const int* __restrict__ dst, int n_edges) {
    int i = blockIdx.x * blockDim.x + threadIdx.x;
    if (i >= n_edges) return;
    int d = dst[i];
    int s = src[i];
    float logit = g_vdot[i] + g_st[s].x + g_st[d].y;
    float e = (logit > 0.f) ? logit : 0.2f * logit;
    int pos = atomicAdd(&g_cur[d], 1);
    g_pcsr[pos] = make_float2(e, __int_as_float(s));
}

// -- warp per node: online softmax + weighted aggregate over fp16 z ------------
__global__ __launch_bounds__(256) void k_aggregate(float* __restrict__ h,
                                                   int n_nodes) {
    int node = (blockIdx.x * blockDim.x + threadIdx.x) >> 5;
    int lane = threadIdx.x & 31;
    if (node >= n_nodes) return;
    int off = g_off[node];
    int deg = g_cnt[node];

    float m = -3.402823466e+38f;
    float S = 0.f;
    for (int j = lane; j < deg; j += 32) {
        float e = g_pcsr[off + j].x;
        float mn = fmaxf(m, e);
        S = S * __expf(m - mn) + __expf(e - mn);
        m = mn;
    }
#pragma unroll
    for (int o = 16; o > 0; o >>= 1) {
        float mo = __shfl_xor_sync(0xFFFFFFFFu, m, o);
        float So = __shfl_xor_sync(0xFFFFFFFFu, S, o);
        float mn = fmaxf(m, mo);
        S = S * __expf(m - mn) + So * __expf(mo - mn);
        m = mn;
    }
    float rS = (deg > 0) ? (1.f / S) : 0.f;

    float4 accA = make_float4(0.f, 0.f, 0.f, 0.f);
    float4 accB = make_float4(0.f, 0.f, 0.f, 0.f);
    int j = 0;
    for (; j + 8 <= deg; j += 8) {
        float2 p[8];
#pragma unroll
        for (int q = 0; q < 8; q++) p[q] = g_pcsr[off + j + q];
        uint2 zr[8];
#pragma unroll
        for (int q = 0; q < 8; q++)
            zr[q] = *(const uint2*)&g_zh[(size_t)__float_as_int(p[q].y) * 64 +
                                         lane * 2];
#pragma unroll
        for (int q = 0; q < 8; q++) {
            float a = __expf(p[q].x - m) * rS;
            float2 f0 = __half22float2(*(__half2*)&zr[q].x);
            float2 f1 = __half22float2(*(__half2*)&zr[q].y);
            float4* acc = (q & 1) ? &accB : &accA;
            acc->x += a * f0.x; acc->y += a * f0.y;
            acc->z += a * f1.x; acc->w += a * f1.y;
        }
    }
    for (; j < deg; j++) {
        float2 p0 = g_pcsr[off + j];
        uint2 zr = *(const uint2*)&g_zh[(size_t)__float_as_int(p0.y) * 64 +
                                        lane * 2];
        float a0 = __expf(p0.x - m) * rS;
        float2 f0 = __half22float2(*(__half2*)&zr.x);
        float2 f1 = __half22float2(*(__half2*)&zr.y);
        accA.x += a0 * f0.x; accA.y += a0 * f0.y;
        accA.z += a0 * f1.x; accA.w += a0 * f1.y;
    }
    accA.x += accB.x; accA.y += accB.y; accA.z += accB.z; accA.w += accB.w;
    *(float4*)&h[(size_t)node * 128 + lane * 4] = accA;
}

extern "C" void kernel_launch(void* const* d_in, const int* in_sizes, int n_in,
                              void* d_out, int out_size) {
    const float* feats_node = (const float*)d_in[0];
    const float* feats_edge = (const float*)d_in[1];
    const float* Wn         = (const float*)d_in[2];
    const float* We         = (const float*)d_in[3];
    const float* Wa         = (const float*)d_in[4];
    const int*   src        = (const int*)d_in[5];
    const int*   dst        = (const int*)d_in[6];
    float*       h          = (float*)d_out;

    int n_nodes = in_sizes[0] / 128;
    int n_edges = in_sizes[5];

    static cudaStream_t s2 = nullptr;
    static cudaEvent_t evFork = nullptr, evJoin = nullptr;
    if (s2 == nullptr) {
        cudaStreamCreateWithFlags(&s2, cudaStreamNonBlocking);
        cudaEventCreateWithFlags(&evFork, cudaEventDisableTiming);
        cudaEventCreateWithFlags(&evJoin, cudaEventDisableTiming);
    }

    k_prep<<<(PAD_NODES + 255) / 256, 256>>>(We, Wa);

    // fork: DRAM-bound edge_dot + tiny scan run concurrent with compute-bound gemm
    cudaEventRecord(evFork, 0);
    cudaStreamWaitEvent(s2, evFork, 0);
    int warps_ed = (n_edges + 7) / 8;
    k_edge_dot<<<(warps_ed + 7) / 8, 256, 0, s2>>>((const float4*)feats_edge,
                                                   dst, n_edges);
    k_scan<<<1, 1024, 0, s2>>>();
    cudaEventRecord(evJoin, s2);

    k_gemm<<<(n_nodes + 63) / 64, 256>>>(feats_node, Wn, Wa, n_nodes);

    cudaStreamWaitEvent(0, evJoin, 0);
    k_build<<<(n_edges + 255) / 256, 256>>>(src, dst, n_edges);
    k_aggregate<<<(n_nodes + 7) / 8, 256>>>(h, n_nodes);
}

// round 12
// speedup vs baseline: 1.1844x; 1.1844x over previous
#include <cuda_runtime.h>
#include <cuda_fp16.h>

// ---------------------------------------------------------------------------
// GAT layer, folded + CSR softmax-aggregate:
//   main:  prep -> edge_dot -> gemm(64x128 tile, 128thr, 8x8/thr, fp16 z,
//          fused st epilogue) -> join -> build -> aggregate
//   s2  :  scan (tiny, 1 block)  [concurrent with gemm only]
// ---------------------------------------------------------------------------

#define MAX_NODES 20000
#define PAD_NODES 20480   /* 1024 * 20 */
#define MAX_EDGES 640000

__device__ __align__(16) __half2 g_zh[MAX_NODES * 64];
__device__ __align__(8)  float2  g_st[MAX_NODES];
__device__ __align__(16) float   g_c[64];
__device__ float                 g_vdot[MAX_EDGES];
__device__ __align__(16) int     g_cnt[PAD_NODES];
__device__ __align__(16) int     g_off[PAD_NODES];
__device__ __align__(16) int     g_cur[PAD_NODES];
__device__ __align__(8) float2   g_pcsr[MAX_EDGES];   // (e, src-as-float-bits)

// -- prep: c = We^T a_e ; zero padded histogram --------------------------------
__global__ void k_prep(const float* __restrict__ We,
                       const float* __restrict__ Wa) {
    int t = blockIdx.x * blockDim.x + threadIdx.x;
    if (t < 64) {
        float acc = 0.f;
#pragma unroll 8
        for (int o = 0; o < 128; o++) acc += We[o * 64 + t] * Wa[256 + o];
        g_c[t] = acc;
    }
    if (t < PAD_NODES) g_cnt[t] = 0;
}

// -- edge feature dot, fully coalesced, 8 edges/warp + fused histogram --------
__global__ __launch_bounds__(256) void k_edge_dot(const float4* __restrict__ fe4,
                                                  const int* __restrict__ dst,
                                                  int n_edges) {
    int w = (blockIdx.x * blockDim.x + threadIdx.x) >> 5;
    int lane = threadIdx.x & 31;
    if (w * 8 >= n_edges) return;
    int total4 = n_edges * 16;
    float4 cc = __ldg((const float4*)g_c + (lane & 15));
    float p[4];
#pragma unroll
    for (int k = 0; k < 4; k++) {
        int idx = w * 128 + k * 32 + lane;
        float4 v = (idx < total4) ? fe4[idx] : make_float4(0.f, 0.f, 0.f, 0.f);
        p[k] = v.x * cc.x + v.y * cc.y + v.z * cc.z + v.w * cc.w;
    }
#pragma unroll
    for (int o = 1; o < 16; o <<= 1) {
#pragma unroll
        for (int k = 0; k < 4; k++)
            p[k] += __shfl_xor_sync(0xFFFFFFFFu, p[k], o);
    }
    if ((lane & 15) == 0) {
        int g = lane >> 4;
#pragma unroll
        for (int k = 0; k < 4; k++) {
            int eid = w * 8 + 2 * k + g;
            if (eid < n_edges) {
                g_vdot[eid] = p[k];
                atomicAdd(&g_cnt[dst[eid]], 1);
            }
        }
    }
}

// -- z = A @ B^T: 64x128 tile, 128 threads, 8x8/thread, float4 LDS -------------
__global__ __launch_bounds__(128) void k_gemm(const float* __restrict__ A,
                                              const float* __restrict__ B,
                                              const float* __restrict__ Wa,
                                              int M) {
    __shared__ float As[16][72];    // padded: 72*4=288B rows, 16B-aligned
    __shared__ float Bs[16][136];   // padded: 136*4=544B rows, 16B-aligned
    const int tid = threadIdx.x;
    const int blockRow = blockIdx.x * 64;
    const int tr = tid >> 4;          // 0..7  -> 8 rows each
    const int tc = tid & 15;          // 0..15 -> 8 cols each
    const int lrow = tid >> 2;        // 0..31
    const int lcol = (tid & 3) * 4;   // 0,4,8,12

    float acc[8][8];
#pragma unroll
    for (int i = 0; i < 8; i++)
#pragma unroll
        for (int j = 0; j < 8; j++) acc[i][j] = 0.f;

    for (int kt = 0; kt < 128; kt += 16) {
        // A tile: 64 rows x 16 cols (2 passes of 32 rows)
#pragma unroll
        for (int h = 0; h < 2; h++) {
            int m = lrow + h * 32;
            int gm = blockRow + m;
            float4 v = (gm < M)
                           ? *(const float4*)&A[(size_t)gm * 128 + kt + lcol]
                           : make_float4(0.f, 0.f, 0.f, 0.f);
            As[lcol + 0][m] = v.x; As[lcol + 1][m] = v.y;
            As[lcol + 2][m] = v.z; As[lcol + 3][m] = v.w;
        }
        // B tile: 128 rows x 16 cols (4 passes of 32 rows)
#pragma unroll
        for (int h = 0; h < 4; h++) {
            int n = lrow + h * 32;
            float4 v = *(const float4*)&B[(size_t)n * 128 + kt + lcol];
            Bs[lcol + 0][n] = v.x; Bs[lcol + 1][n] = v.y;
            Bs[lcol + 2][n] = v.z; Bs[lcol + 3][n] = v.w;
        }
        __syncthreads();
#pragma unroll
        for (int k = 0; k < 16; k++) {
            float4 a0 = *(const float4*)&As[k][tr * 8];
            float4 a1 = *(const float4*)&As[k][tr * 8 + 4];
            float4 b0 = *(const float4*)&Bs[k][tc * 8];
            float4 b1 = *(const float4*)&Bs[k][tc * 8 + 4];
            float ra[8] = {a0.x, a0.y, a0.z, a0.w, a1.x, a1.y, a1.z, a1.w};
            float rb[8] = {b0.x, b0.y, b0.z, b0.w, b1.x, b1.y, b1.z, b1.w};
#pragma unroll
            for (int i = 0; i < 8; i++)
#pragma unroll
                for (int j = 0; j < 8; j++) acc[i][j] += ra[i] * rb[j];
        }
        __syncthreads();
    }

    // store z tile as fp16
#pragma unroll
    for (int i = 0; i < 8; i++) {
        int gm = blockRow + tr * 8 + i;
        if (gm < M) {
            __half2 q[4];
#pragma unroll
            for (int j = 0; j < 4; j++)
                q[j] = __float22half2_rn(
                    make_float2(acc[i][2 * j], acc[i][2 * j + 1]));
            *(uint4*)&g_zh[(size_t)gm * 64 + tc * 4] = *(uint4*)q;
        }
    }

    // fused epilogue: per-row dots with a_src / a_dst (16-lane reduce)
    float asv[8], adv[8];
#pragma unroll
    for (int j = 0; j < 8; j++) {
        asv[j] = __ldg(Wa + tc * 8 + j);
        adv[j] = __ldg(Wa + 128 + tc * 8 + j);
    }
#pragma unroll
    for (int i = 0; i < 8; i++) {
        float s = 0.f, t = 0.f;
#pragma unroll
        for (int j = 0; j < 8; j++) {
            s += acc[i][j] * asv[j];
            t += acc[i][j] * adv[j];
        }
#pragma unroll
        for (int o = 1; o < 16; o <<= 1) {
            s += __shfl_xor_sync(0xFFFFFFFFu, s, o);
            t += __shfl_xor_sync(0xFFFFFFFFu, t, o);
        }
        int gm = blockRow + tr * 8 + i;
        if (tc == 0 && gm < M) g_st[gm] = make_float2(s, t);
    }
}

// -- exclusive scan over padded 20480 (runs on s2, concurrent with gemm) -------
__global__ __launch_bounds__(1024) void k_scan() {
    __shared__ int wsum[32];
    const int tid = threadIdx.x;
    const int lane = tid & 31, wid = tid >> 5;
    const int lo = tid * 20;

    int vals[20];
#pragma unroll
    for (int k = 0; k < 5; k++) {
        int4 v = *(const int4*)&g_cnt[lo + k * 4];
        vals[k * 4 + 0] = v.x; vals[k * 4 + 1] = v.y;
        vals[k * 4 + 2] = v.z; vals[k * 4 + 3] = v.w;
    }

    int local = 0;
#pragma unroll
    for (int i = 0; i < 20; i++) local += vals[i];

    int v = local;
#pragma unroll
    for (int o = 1; o < 32; o <<= 1) {
        int u = __shfl_up_sync(0xFFFFFFFFu, v, o);
        if (lane >= o) v += u;
    }
    if (lane == 31) wsum[wid] = v;
    __syncthreads();
    if (wid == 0) {
        int wv = wsum[lane];
#pragma unroll
        for (int o = 1; o < 32; o <<= 1) {
            int u = __shfl_up_sync(0xFFFFFFFFu, wv, o);
            if (lane >= o) wv += u;
        }
        wsum[lane] = wv;
    }
    __syncthreads();
    int run = v - local + (wid > 0 ? wsum[wid - 1] : 0);

    int pref[20];
#pragma unroll
    for (int i = 0; i < 20; i++) { pref[i] = run; run += vals[i]; }
#pragma unroll
    for (int k = 0; k < 5; k++) {
        int4 pv = make_int4(pref[k * 4 + 0], pref[k * 4 + 1],
                            pref[k * 4 + 2], pref[k * 4 + 3]);
        *(int4*)&g_off[lo + k * 4] = pv;
        *(int4*)&g_cur[lo + k * 4] = pv;
    }
}

// -- build CSR-ordered packed (e, src), fused logit + leaky-relu ---------------
__global__ void k_build(const int* __restrict__ src,
                        const int* __restrict__ dst, int n_edges) {
    int i = blockIdx.x * blockDim.x + threadIdx.x;
    if (i >= n_edges) return;
    int d = dst[i];
    int s = src[i];
    float logit = g_vdot[i] + g_st[s].x + g_st[d].y;
    float e = (logit > 0.f) ? logit : 0.2f * logit;
    int pos = atomicAdd(&g_cur[d], 1);
    g_pcsr[pos] = make_float2(e, __int_as_float(s));
}

// -- warp per node: online softmax + weighted aggregate over fp16 z ------------
__global__ __launch_bounds__(256) void k_aggregate(float* __restrict__ h,
                                                   int n_nodes) {
    int node = (blockIdx.x * blockDim.x + threadIdx.x) >> 5;
    int lane = threadIdx.x & 31;
    if (node >= n_nodes) return;
    int off = g_off[node];
    int deg = g_cnt[node];

    float m = -3.402823466e+38f;
    float S = 0.f;
    for (int j = lane; j < deg; j += 32) {
        float e = g_pcsr[off + j].x;
        float mn = fmaxf(m, e);
        S = S * __expf(m - mn) + __expf(e - mn);
        m = mn;
    }
#pragma unroll
    for (int o = 16; o > 0; o >>= 1) {
        float mo = __shfl_xor_sync(0xFFFFFFFFu, m, o);
        float So = __shfl_xor_sync(0xFFFFFFFFu, S, o);
        float mn = fmaxf(m, mo);
        S = S * __expf(m - mn) + So * __expf(mo - mn);
        m = mn;
    }
    float rS = (deg > 0) ? (1.f / S) : 0.f;

    float4 accA = make_float4(0.f, 0.f, 0.f, 0.f);
    float4 accB = make_float4(0.f, 0.f, 0.f, 0.f);
    int j = 0;
    for (; j + 8 <= deg; j += 8) {
        float2 p[8];
#pragma unroll
        for (int q = 0; q < 8; q++) p[q] = g_pcsr[off + j + q];
        uint2 zr[8];
#pragma unroll
        for (int q = 0; q < 8; q++)
            zr[q] = *(const uint2*)&g_zh[(size_t)__float_as_int(p[q].y) * 64 +
                                         lane * 2];
#pragma unroll
        for (int q = 0; q < 8; q++) {
            float a = __expf(p[q].x - m) * rS;
            float2 f0 = __half22float2(*(__half2*)&zr[q].x);
            float2 f1 = __half22float2(*(__half2*)&zr[q].y);
            float4* acc = (q & 1) ? &accB : &accA;
            acc->x += a * f0.x; acc->y += a * f0.y;
            acc->z += a * f1.x; acc->w += a * f1.y;
        }
    }
    for (; j < deg; j++) {
        float2 p0 = g_pcsr[off + j];
        uint2 zr = *(const uint2*)&g_zh[(size_t)__float_as_int(p0.y) * 64 +
                                        lane * 2];
        float a0 = __expf(p0.x - m) * rS;
        float2 f0 = __half22float2(*(__half2*)&zr.x);
        float2 f1 = __half22float2(*(__half2*)&zr.y);
        accA.x += a0 * f0.x; accA.y += a0 * f0.y;
        accA.z += a0 * f1.x; accA.w += a0 * f1.y;
    }
    accA.x += accB.x; accA.y += accB.y; accA.z += accB.z; accA.w += accB.w;
    *(float4*)&h[(size_t)node * 128 + lane * 4] = accA;
}

extern "C" void kernel_launch(void* const* d_in, const int* in_sizes, int n_in,
                              void* d_out, int out_size) {
    const float* feats_node = (const float*)d_in[0];
    const float* feats_edge = (const float*)d_in[1];
    const float* Wn         = (const float*)d_in[2];
    const float* We         = (const float*)d_in[3];
    const float* Wa         = (const float*)d_in[4];
    const int*   src        = (const int*)d_in[5];
    const int*   dst        = (const int*)d_in[6];
    float*       h          = (float*)d_out;

    int n_nodes = in_sizes[0] / 128;
    int n_edges = in_sizes[5];

    static cudaStream_t s2 = nullptr;
    static cudaEvent_t evFork = nullptr, evJoin = nullptr;
    if (s2 == nullptr) {
        cudaStreamCreateWithFlags(&s2, cudaStreamNonBlocking);
        cudaEventCreateWithFlags(&evFork, cudaEventDisableTiming);
        cudaEventCreateWithFlags(&evJoin, cudaEventDisableTiming);
    }

    k_prep<<<(PAD_NODES + 255) / 256, 256>>>(We, Wa);

    // edge_dot SERIAL on main stream (overlap with gemm is destructive: R6, R11)
    int warps_ed = (n_edges + 7) / 8;
    k_edge_dot<<<(warps_ed + 7) / 8, 256>>>((const float4*)feats_edge, dst,
                                            n_edges);

    // fork: tiny single-block scan runs concurrently with compute-bound gemm
    cudaEventRecord(evFork, 0);
    cudaStreamWaitEvent(s2, evFork, 0);
    k_scan<<<1, 1024, 0, s2>>>();
    cudaEventRecord(evJoin, s2);

    k_gemm<<<(n_nodes + 63) / 64, 128>>>(feats_node, Wn, Wa, n_nodes);

    cudaStreamWaitEvent(0, evJoin, 0);
    k_build<<<(n_edges + 255) / 256, 256>>>(src, dst, n_edges);
    k_aggregate<<<(n_nodes + 7) / 8, 256>>>(h, n_nodes);
}

// round 13
// speedup vs baseline: 1.2802x; 1.0809x over previous
#include <cuda_runtime.h>
#include <cuda_fp16.h>

// ---------------------------------------------------------------------------
// GAT layer, fully folded + CSR softmax-aggregate, overlapped:
//   c = We^T a_e ; u = Wn^T a_src ; v = Wn^T a_dst   (all attention GEMMs folded)
//   node_st : st[i] = (feats_node[i].u, feats_node[i].v)   [fp32-exact, no gemm]
//   edge_dot: vdot_k = feats_edge[k].c (coalesced) + dst histogram
//   fork s2 : scan -> build(e = lrelu(vdot+st), CSR scatter)   HIDDEN UNDER gemm
//   main    : gemm z = feats_node @ Wn^T (fp16 store, no epilogue)
//   join -> aggregate: warp/node online softmax + h = sum alpha*z[src]
// ---------------------------------------------------------------------------

#define MAX_NODES 20000
#define PAD_NODES 20480   /* 1024 * 20 */
#define MAX_EDGES 640000

__device__ __align__(16) __half2 g_zh[MAX_NODES * 64];
__device__ __align__(8)  float2  g_st[MAX_NODES];
__device__ __align__(16) float   g_c[64];
__device__ __align__(16) float   g_u[128];
__device__ __align__(16) float   g_v[128];
__device__ float                 g_vdot[MAX_EDGES];
__device__ __align__(16) int     g_cnt[PAD_NODES];
__device__ __align__(16) int     g_off[PAD_NODES];
__device__ __align__(16) int     g_cur[PAD_NODES];
__device__ __align__(8) float2   g_pcsr[MAX_EDGES];   // (e, src-as-float-bits)

// -- weights: c = We^T a_e ; u = Wn^T a_src ; v = Wn^T a_dst (1 block) ---------
__global__ void k_weights(const float* __restrict__ Wn,
                          const float* __restrict__ We,
                          const float* __restrict__ Wa) {
    int t = threadIdx.x;
    if (t < 64) {
        float acc = 0.f;
#pragma unroll 8
        for (int o = 0; o < 128; o++) acc += We[o * 64 + t] * Wa[256 + o];
        g_c[t] = acc;
    }
    if (t < 128) {
        float acc = 0.f;
#pragma unroll 8
        for (int o = 0; o < 128; o++) acc += Wn[o * 128 + t] * Wa[o];
        g_u[t] = acc;
    } else {
        int tt = t - 128;
        float acc = 0.f;
#pragma unroll 8
        for (int o = 0; o < 128; o++) acc += Wn[o * 128 + tt] * Wa[128 + o];
        g_v[tt] = acc;
    }
}

// -- zero padded histogram ------------------------------------------------------
__global__ void k_zero() {
    int t = blockIdx.x * blockDim.x + threadIdx.x;
    if (t < PAD_NODES) g_cnt[t] = 0;
}

// -- per-node st: warp per node, coalesced 512B row, fp32-exact ------------------
__global__ __launch_bounds__(256) void k_node_st(const float* __restrict__ fn,
                                                 int n_nodes) {
    int node = (blockIdx.x * blockDim.x + threadIdx.x) >> 5;
    int lane = threadIdx.x & 31;
    if (node >= n_nodes) return;
    float4 x = *(const float4*)&fn[(size_t)node * 128 + lane * 4];
    float4 uu = __ldg((const float4*)g_u + lane);
    float4 vv = __ldg((const float4*)g_v + lane);
    float s = x.x * uu.x + x.y * uu.y + x.z * uu.z + x.w * uu.w;
    float t = x.x * vv.x + x.y * vv.y + x.z * vv.z + x.w * vv.w;
#pragma unroll
    for (int o = 16; o > 0; o >>= 1) {
        s += __shfl_xor_sync(0xFFFFFFFFu, s, o);
        t += __shfl_xor_sync(0xFFFFFFFFu, t, o);
    }
    if (lane == 0) g_st[node] = make_float2(s, t);
}

// -- edge feature dot, fully coalesced, 8 edges/warp + fused histogram ----------
__global__ __launch_bounds__(256) void k_edge_dot(const float4* __restrict__ fe4,
                                                  const int* __restrict__ dst,
                                                  int n_edges) {
    int w = (blockIdx.x * blockDim.x + threadIdx.x) >> 5;
    int lane = threadIdx.x & 31;
    if (w * 8 >= n_edges) return;
    int total4 = n_edges * 16;
    float4 cc = __ldg((const float4*)g_c + (lane & 15));
    float p[4];
#pragma unroll
    for (int k = 0; k < 4; k++) {
        int idx = w * 128 + k * 32 + lane;
        float4 v = (idx < total4) ? fe4[idx] : make_float4(0.f, 0.f, 0.f, 0.f);
        p[k] = v.x * cc.x + v.y * cc.y + v.z * cc.z + v.w * cc.w;
    }
#pragma unroll
    for (int o = 1; o < 16; o <<= 1) {
#pragma unroll
        for (int k = 0; k < 4; k++)
            p[k] += __shfl_xor_sync(0xFFFFFFFFu, p[k], o);
    }
    if ((lane & 15) == 0) {
        int g = lane >> 4;
#pragma unroll
        for (int k = 0; k < 4; k++) {
            int eid = w * 8 + 2 * k + g;
            if (eid < n_edges) {
                g_vdot[eid] = p[k];
                atomicAdd(&g_cnt[dst[eid]], 1);
            }
        }
    }
}

// -- z = A @ B^T: 64x128 tile, 128 threads, 8x8/thread, float4 LDS, no epilogue -
__global__ __launch_bounds__(128) void k_gemm(const float* __restrict__ A,
                                              const float* __restrict__ B,
                                              int M) {
    __shared__ float As[16][72];
    __shared__ float Bs[16][136];
    const int tid = threadIdx.x;
    const int blockRow = blockIdx.x * 64;
    const int tr = tid >> 4;
    const int tc = tid & 15;
    const int lrow = tid >> 2;
    const int lcol = (tid & 3) * 4;

    float acc[8][8];
#pragma unroll
    for (int i = 0; i < 8; i++)
#pragma unroll
        for (int j = 0; j < 8; j++) acc[i][j] = 0.f;

    for (int kt = 0; kt < 128; kt += 16) {
#pragma unroll
        for (int h = 0; h < 2; h++) {
            int m = lrow + h * 32;
            int gm = blockRow + m;
            float4 v = (gm < M)
                           ? *(const float4*)&A[(size_t)gm * 128 + kt + lcol]
                           : make_float4(0.f, 0.f, 0.f, 0.f);
            As[lcol + 0][m] = v.x; As[lcol + 1][m] = v.y;
            As[lcol + 2][m] = v.z; As[lcol + 3][m] = v.w;
        }
#pragma unroll
        for (int h = 0; h < 4; h++) {
            int n = lrow + h * 32;
            float4 v = *(const float4*)&B[(size_t)n * 128 + kt + lcol];
            Bs[lcol + 0][n] = v.x; Bs[lcol + 1][n] = v.y;
            Bs[lcol + 2][n] = v.z; Bs[lcol + 3][n] = v.w;
        }
        __syncthreads();
#pragma unroll
        for (int k = 0; k < 16; k++) {
            float4 a0 = *(const float4*)&As[k][tr * 8];
            float4 a1 = *(const float4*)&As[k][tr * 8 + 4];
            float4 b0 = *(const float4*)&Bs[k][tc * 8];
            float4 b1 = *(const float4*)&Bs[k][tc * 8 + 4];
            float ra[8] = {a0.x, a0.y, a0.z, a0.w, a1.x, a1.y, a1.z, a1.w};
            float rb[8] = {b0.x, b0.y, b0.z, b0.w, b1.x, b1.y, b1.z, b1.w};
#pragma unroll
            for (int i = 0; i < 8; i++)
#pragma unroll
                for (int j = 0; j < 8; j++) acc[i][j] += ra[i] * rb[j];
        }
        __syncthreads();
    }

#pragma unroll
    for (int i = 0; i < 8; i++) {
        int gm = blockRow + tr * 8 + i;
        if (gm < M) {
            __half2 q[4];
#pragma unroll
            for (int j = 0; j < 4; j++)
                q[j] = __float22half2_rn(
                    make_float2(acc[i][2 * j], acc[i][2 * j + 1]));
            *(uint4*)&g_zh[(size_t)gm * 64 + tc * 4] = *(uint4*)q;
        }
    }
}

// -- exclusive scan over padded 20480 (s2, hidden under gemm) -------------------
__global__ __launch_bounds__(1024) void k_scan() {
    __shared__ int wsum[32];
    const int tid = threadIdx.x;
    const int lane = tid & 31, wid = tid >> 5;
    const int lo = tid * 20;

    int vals[20];
#pragma unroll
    for (int k = 0; k < 5; k++) {
        int4 v = *(const int4*)&g_cnt[lo + k * 4];
        vals[k * 4 + 0] = v.x; vals[k * 4 + 1] = v.y;
        vals[k * 4 + 2] = v.z; vals[k * 4 + 3] = v.w;
    }

    int local = 0;
#pragma unroll
    for (int i = 0; i < 20; i++) local += vals[i];

    int v = local;
#pragma unroll
    for (int o = 1; o < 32; o <<= 1) {
        int u = __shfl_up_sync(0xFFFFFFFFu, v, o);
        if (lane >= o) v += u;
    }
    if (lane == 31) wsum[wid] = v;
    __syncthreads();
    if (wid == 0) {
        int wv = wsum[lane];
#pragma unroll
        for (int o = 1; o < 32; o <<= 1) {
            int u = __shfl_up_sync(0xFFFFFFFFu, wv, o);
            if (lane >= o) wv += u;
        }
        wsum[lane] = wv;
    }
    __syncthreads();
    int run = v - local + (wid > 0 ? wsum[wid - 1] : 0);

    int pref[20];
#pragma unroll
    for (int i = 0; i < 20; i++) { pref[i] = run; run += vals[i]; }
#pragma unroll
    for (int k = 0; k < 5; k++) {
        int4 pv = make_int4(pref[k * 4 + 0], pref[k * 4 + 1],
                            pref[k * 4 + 2], pref[k * 4 + 3]);
        *(int4*)&g_off[lo + k * 4] = pv;
        *(int4*)&g_cur[lo + k * 4] = pv;
    }
}

// -- build CSR-ordered packed (e, src), fused logit + leaky-relu (s2) -----------
__global__ void k_build(const int* __restrict__ src,
                        const int* __restrict__ dst, int n_edges) {
    int i = blockIdx.x * blockDim.x + threadIdx.x;
    if (i >= n_edges) return;
    int d = dst[i];
    int s = src[i];
    float logit = g_vdot[i] + g_st[s].x + g_st[d].y;
    float e = (logit > 0.f) ? logit : 0.2f * logit;
    int pos = atomicAdd(&g_cur[d], 1);
    g_pcsr[pos] = make_float2(e, __int_as_float(s));
}

// -- warp per node: online softmax + weighted aggregate over fp16 z -------------
__global__ __launch_bounds__(256) void k_aggregate(float* __restrict__ h,
                                                   int n_nodes) {
    int node = (blockIdx.x * blockDim.x + threadIdx.x) >> 5;
    int lane = threadIdx.x & 31;
    if (node >= n_nodes) return;
    int off = g_off[node];
    int deg = g_cnt[node];

    float m = -3.402823466e+38f;
    float S = 0.f;
    for (int j = lane; j < deg; j += 32) {
        float e = g_pcsr[off + j].x;
        float mn = fmaxf(m, e);
        S = S * __expf(m - mn) + __expf(e - mn);
        m = mn;
    }
#pragma unroll
    for (int o = 16; o > 0; o >>= 1) {
        float mo = __shfl_xor_sync(0xFFFFFFFFu, m, o);
        float So = __shfl_xor_sync(0xFFFFFFFFu, S, o);
        float mn = fmaxf(m, mo);
        S = S * __expf(m - mn) + So * __expf(mo - mn);
        m = mn;
    }
    float rS = (deg > 0) ? (1.f / S) : 0.f;

    float4 accA = make_float4(0.f, 0.f, 0.f, 0.f);
    float4 accB = make_float4(0.f, 0.f, 0.f, 0.f);
    int j = 0;
    for (; j + 8 <= deg; j += 8) {
        float2 p[8];
#pragma unroll
        for (int q = 0; q < 8; q++) p[q] = g_pcsr[off + j + q];
        uint2 zr[8];
#pragma unroll
        for (int q = 0; q < 8; q++)
            zr[q] = *(const uint2*)&g_zh[(size_t)__float_as_int(p[q].y) * 64 +
                                         lane * 2];
#pragma unroll
        for (int q = 0; q < 8; q++) {
            float a = __expf(p[q].x - m) * rS;
            float2 f0 = __half22float2(*(__half2*)&zr[q].x);
            float2 f1 = __half22float2(*(__half2*)&zr[q].y);
            float4* acc = (q & 1) ? &accB : &accA;
            acc->x += a * f0.x; acc->y += a * f0.y;
            acc->z += a * f1.x; acc->w += a * f1.y;
        }
    }
    for (; j < deg; j++) {
        float2 p0 = g_pcsr[off + j];
        uint2 zr = *(const uint2*)&g_zh[(size_t)__float_as_int(p0.y) * 64 +
                                        lane * 2];
        float a0 = __expf(p0.x - m) * rS;
        float2 f0 = __half22float2(*(__half2*)&zr.x);
        float2 f1 = __half22float2(*(__half2*)&zr.y);
        accA.x += a0 * f0.x; accA.y += a0 * f0.y;
        accA.z += a0 * f1.x; accA.w += a0 * f1.y;
    }
    accA.x += accB.x; accA.y += accB.y; accA.z += accB.z; accA.w += accB.w;
    *(float4*)&h[(size_t)node * 128 + lane * 4] = accA;
}

extern "C" void kernel_launch(void* const* d_in, const int* in_sizes, int n_in,
                              void* d_out, int out_size) {
    const float* feats_node = (const float*)d_in[0];
    const float* feats_edge = (const float*)d_in[1];
    const float* Wn         = (const float*)d_in[2];
    const float* We         = (const float*)d_in[3];
    const float* Wa         = (const float*)d_in[4];
    const int*   src        = (const int*)d_in[5];
    const int*   dst        = (const int*)d_in[6];
    float*       h          = (float*)d_out;

    int n_nodes = in_sizes[0] / 128;
    int n_edges = in_sizes[5];

    static cudaStream_t s2 = nullptr;
    static cudaEvent_t evFork = nullptr, evJoin = nullptr;
    if (s2 == nullptr) {
        cudaStreamCreateWithFlags(&s2, cudaStreamNonBlocking);
        cudaEventCreateWithFlags(&evFork, cudaEventDisableTiming);
        cudaEventCreateWithFlags(&evJoin, cudaEventDisableTiming);
    }

    k_weights<<<1, 256>>>(Wn, We, Wa);
    k_zero<<<(PAD_NODES + 255) / 256, 256>>>();
    k_node_st<<<(n_nodes + 7) / 8, 256>>>(feats_node, n_nodes);
    int warps_ed = (n_edges + 7) / 8;
    k_edge_dot<<<(warps_ed + 7) / 8, 256>>>((const float4*)feats_edge, dst,
                                            n_edges);

    // fork: scan+build (latency-bound, ~22us) hidden under compute-bound gemm
    cudaEventRecord(evFork, 0);
    cudaStreamWaitEvent(s2, evFork, 0);
    k_scan<<<1, 1024, 0, s2>>>();
    k_build<<<(n_edges + 255) / 256, 256, 0, s2>>>(src, dst, n_edges);
    cudaEventRecord(evJoin, s2);

    k_gemm<<<(n_nodes + 63) / 64, 128>>>(feats_node, Wn, n_nodes);

    cudaStreamWaitEvent(0, evJoin, 0);
    k_aggregate<<<(n_nodes + 7) / 8, 256>>>(h, n_nodes);
}